// round 3
// baseline (speedup 1.0000x reference)
#include <cuda_runtime.h>
#include <cuda_bf16.h>

// ---------------------------------------------------------------------------
// SphericalHarmonicTransform, L=10, N=2e6 points -> 121 coefficients.
// Single fused kernel: grid-stride accumulation + block reduce + last-block
// (atomic ticket) final reduction in fp64 with epilogue scaling.
//
// Identities:
//   z1 = (-x/2,-y/2), z2 = -conj(z1)
//   zreal(p,q) = zr[p]^2 - zi[q]^2
//   zimag(p,q)*(-1)^q = v^q * zi[m],  v = -|z1|^2, m = p-q
//   term(l,p,q) = D * B(p,q) * w[k] * h[l-k],  w[k]=mask*z0*r^k, h[s]=r^s/s!
//   A(l,m) scaling applied once in the epilogue.
// (re,im) channels of each m>0 accumulator packed into one fma.rn.f32x2.
// ---------------------------------------------------------------------------

#define NBLK 304
#define NTHR 256

__device__ float g_part[121 * NBLK];     // per-block partials, [j][block]
__device__ unsigned int g_ticket = 0;    // last-block election

// ----- compile-time math -----
__host__ __device__ constexpr double cfact(int n) {
    double r = 1.0;
    for (int i = 2; i <= n; ++i) r *= (double)i;
    return r;
}
__host__ __device__ constexpr float cB(int p, int q) {
    return (float)(1.0 / (cfact(p) * cfact(q)));
}

// ----- compile-time for -----
template <int N> struct IntC { static constexpr int value = N; };
template <int Start, int End, class F>
__device__ __forceinline__ void static_for(F&& f) {
    if constexpr (Start < End) {
        f(IntC<Start>{});
        static_for<Start + 1, End>(static_cast<F&&>(f));
    }
}

// ----- packed f32x2 helpers -----
__device__ __forceinline__ unsigned long long pack2(float lo, float hi) {
    unsigned long long r;
    asm("mov.b64 %0, {%1, %2};" : "=l"(r) : "f"(lo), "f"(hi));
    return r;
}
__device__ __forceinline__ void unpack2(unsigned long long v, float& lo, float& hi) {
    asm("mov.b64 {%0, %1}, %2;" : "=f"(lo), "=f"(hi) : "l"(v));
}
__device__ __forceinline__ unsigned long long fma2(unsigned long long a,
                                                   unsigned long long b,
                                                   unsigned long long c) {
    unsigned long long d;
    asm("fma.rn.f32x2 %0, %1, %2, %3;" : "=l"(d) : "l"(a), "l"(b), "l"(c));
    return d;
}

// acc2 index for (l, m>0)
__host__ __device__ constexpr int aidx(int l, int m) { return l * (l - 1) / 2 + (m - 1); }

// ---------------------------------------------------------------------------
__global__ __launch_bounds__(NTHR, 1)
void sht_fused_kernel(const float* __restrict__ pos, int npts,
                      float* __restrict__ out) {
    unsigned long long acc2[55];   // (l,m>0): lo = +m (real), hi = -m (imag)
    float acc0[11];                // m == 0
#pragma unroll
    for (int j = 0; j < 55; ++j) acc2[j] = 0ull;
#pragma unroll
    for (int j = 0; j < 11; ++j) acc0[j] = 0.0f;

    const int stride = gridDim.x * blockDim.x;
    for (int i = blockIdx.x * blockDim.x + threadIdx.x; i < npts; i += stride) {
        const float x  = pos[3 * i + 0];
        const float y  = pos[3 * i + 1];
        const float z0 = pos[3 * i + 2];

        const float xy2 = fmaf(x, x, y * y);
        const float r2  = fmaf(z0, z0, xy2);
        const float r   = sqrtf(r2);

        // w[k] = mask * z0 * r^k
        float w[11];
        w[0] = (r2 > 0.0f) ? z0 : 0.0f;
#pragma unroll
        for (int k = 1; k < 11; ++k) w[k] = w[k - 1] * r;

        // h[s] = r^s/s!, broadcast-packed h2
        float h[11];
        unsigned long long h2[11];
        h[0] = 1.0f;
        h2[0] = pack2(1.0f, 1.0f);
        static_for<1, 11>([&](auto sc) {
            constexpr int s = decltype(sc)::value;
            const float rs = r * (float)(1.0 / (double)s);   // FMUL-imm
            h[s] = h[s - 1] * rs;
            h2[s] = pack2(h[s], h[s]);
        });

        // z1^p powers, z1 = (-x/2, -y/2)
        float zr[11], zi[11];
        zr[0] = 1.0f; zi[0] = 0.0f;
        const float ar = -0.5f * x;
        const float ai = -0.5f * y;
#pragma unroll
        for (int p = 1; p < 11; ++p) {
            zr[p] = fmaf(ar, zr[p - 1], -(ai * zi[p - 1]));
            zi[p] = fmaf(ar, zi[p - 1],  (ai * zr[p - 1]));
        }

        // squares: sr[0..10], si[0..5] (q <= 5 only)
        float sr[11], si[6];
#pragma unroll
        for (int p = 0; p < 11; ++p) sr[p] = zr[p] * zr[p];
#pragma unroll
        for (int q = 0; q < 6; ++q) si[q] = zi[q] * zi[q];

        // vq[q] = (-|z1|^2)^q, q = 0..4 (m>0 pairs only)
        float vq[5];
        vq[0] = 1.0f;
        vq[1] = -0.25f * xy2;
        vq[2] = vq[1] * vq[1];
        vq[3] = vq[2] * vq[1];
        vq[4] = vq[2] * vq[2];

        // 36 (p,q) pairs, p >= q, k = p+q <= 10
        static_for<0, 11>([&](auto pc) {
            constexpr int p = decltype(pc)::value;
            static_for<0, p + 1>([&](auto qc) {
                constexpr int q = decltype(qc)::value;
                if constexpr (p + q <= 10) {
                    constexpr int k = p + q;
                    constexpr int m = p - q;
                    const float D = sr[p] - si[q];
                    const float c = w[k] * cB(p, q);           // FMUL-imm
                    if constexpr (m == 0) {
                        const float Dc = D * c;
                        static_for<k, 11>([&](auto lc) {
                            constexpr int l = decltype(lc)::value;
                            acc0[l] = fmaf(Dc, h[l - k], acc0[l]);
                        });
                    } else {
                        // signed imag factor: P = v^q * zi[m]
                        const float vqc = vq[q] * c;
                        const float Pc  = vqc * zi[m];
                        const unsigned long long DPs = pack2(D * c, Pc);
                        static_for<k, 11>([&](auto lc) {
                            constexpr int l = decltype(lc)::value;
                            acc2[aidx(l, m)] = fma2(DPs, h2[l - k], acc2[aidx(l, m)]);
                        });
                    }
                }
            });
        });
    }

    // ---- block-level reduction: shfl within warp, smem across 8 warps ----
    __shared__ float sred[NTHR / 32][121];
    const int lane = threadIdx.x & 31;
    const int wid  = threadIdx.x >> 5;

    auto wreduce = [&](float v, int j) {
#pragma unroll
        for (int o = 16; o > 0; o >>= 1) v += __shfl_xor_sync(0xffffffffu, v, o);
        if (lane == 0) sred[wid][j] = v;
    };

    static_for<0, 11>([&](auto lc) {
        constexpr int l = decltype(lc)::value;
        wreduce(acc0[l], l * l + l);
        static_for<1, l + 1>([&](auto mc) {
            constexpr int m = decltype(mc)::value;
            float re, im;
            unpack2(acc2[aidx(l, m)], re, im);
            wreduce(re, l * l + l + m);
            wreduce(im, l * l + l - m);
        });
    });
    __syncthreads();

    if (threadIdx.x < 121) {
        float s = 0.0f;
#pragma unroll
        for (int wv = 0; wv < NTHR / 32; ++wv) s += sred[wv][threadIdx.x];
        g_part[threadIdx.x * NBLK + blockIdx.x] = s;
    }

    // ---- last block does the final reduction + epilogue scaling ----
    __threadfence();
    __shared__ int amLast;
    if (threadIdx.x == 0)
        amLast = (atomicAdd(&g_ticket, 1u) == (unsigned)(gridDim.x - 1));
    __syncthreads();

    if (amLast) {
        // 242 active threads: j = t>>1 coefficient, half = t&1 block range
        double s = 0.0;
        const int j = threadIdx.x >> 1;
        const int hb = threadIdx.x & 1;
        if (threadIdx.x < 242) {
            const int b0 = hb * (NBLK / 2);
#pragma unroll 4
            for (int b = b0; b < b0 + NBLK / 2; ++b)
                s += (double)g_part[j * NBLK + b];
        }
        // combine adjacent-lane halves
        s += __shfl_xor_sync(0xffffffffu, s, 1);
        if (threadIdx.x < 242 && hb == 0) {
            // scale A(l,m) = sqrt((l+|m|)!(l-|m|)!) * sqrt((2l+1)/4pi) * f(m)
            int l = 0;
            while ((l + 1) * (l + 1) <= j) ++l;
            const int M  = j - l * l - l;
            const int am = (M < 0) ? -M : M;
            double f1 = 1.0, f2 = 1.0;
            for (int t = 2; t <= l + am; ++t) f1 *= (double)t;
            for (int t = 2; t <= l - am; ++t) f2 *= (double)t;
            double scale = sqrt(f1) * sqrt(f2) *
                           sqrt((2.0 * l + 1.0) / (4.0 * 3.14159265358979323846));
            if (am) scale *= sqrt(2.0) * ((am & 1) ? -1.0 : 1.0);
            out[j] = (float)(s * scale);
        }
        if (threadIdx.x == 0) g_ticket = 0;   // reset for next graph replay
    }
}

// ---------------------------------------------------------------------------
extern "C" void kernel_launch(void* const* d_in, const int* in_sizes, int n_in,
                              void* d_out, int out_size) {
    const float* pos = (const float*)d_in[0];
    const int npts = in_sizes[0] / 3;
    sht_fused_kernel<<<NBLK, NTHR>>>(pos, npts, (float*)d_out);
}

// round 4
// speedup vs baseline: 1.0293x; 1.0293x over previous
#include <cuda_runtime.h>
#include <cuda_bf16.h>

// ---------------------------------------------------------------------------
// SphericalHarmonicTransform, L=10, N=2e6 points -> 121 coefficients.
// Fused single kernel; explicit software-prefetched point loads.
//
//   z1 = (-x/2,-y/2), z2 = -conj(z1)
//   zreal(p,q) = zr[p]^2 - zi[q]^2
//   term(l,p,q) = D * B(p,q) * w[k] * h[l-k], w[k]=mask*z0*r^k, h[s]=r^s/s!
//   A(l,m) applied once in the last-block epilogue.
// (re,im) channels of each m>0 accumulator packed into one fma.rn.f32x2.
// ---------------------------------------------------------------------------

#define NBLK 304
#define NTHR 256

__device__ float g_part[121 * NBLK];     // per-block partials, [j][block]
__device__ unsigned int g_ticket = 0;    // last-block election

// ----- compile-time math -----
__host__ __device__ constexpr double cfact(int n) {
    double r = 1.0;
    for (int i = 2; i <= n; ++i) r *= (double)i;
    return r;
}
__host__ __device__ constexpr float cB(int p, int q) {
    return (float)(1.0 / (cfact(p) * cfact(q)));
}

// ----- compile-time for -----
template <int N> struct IntC { static constexpr int value = N; };
template <int Start, int End, class F>
__device__ __forceinline__ void static_for(F&& f) {
    if constexpr (Start < End) {
        f(IntC<Start>{});
        static_for<Start + 1, End>(static_cast<F&&>(f));
    }
}

// ----- packed f32x2 helpers -----
__device__ __forceinline__ unsigned long long pack2(float lo, float hi) {
    unsigned long long r;
    asm("mov.b64 %0, {%1, %2};" : "=l"(r) : "f"(lo), "f"(hi));
    return r;
}
__device__ __forceinline__ void unpack2(unsigned long long v, float& lo, float& hi) {
    asm("mov.b64 {%0, %1}, %2;" : "=f"(lo), "=f"(hi) : "l"(v));
}
__device__ __forceinline__ unsigned long long fma2(unsigned long long a,
                                                   unsigned long long b,
                                                   unsigned long long c) {
    unsigned long long d;
    asm("fma.rn.f32x2 %0, %1, %2, %3;" : "=l"(d) : "l"(a), "l"(b), "l"(c));
    return d;
}

__host__ __device__ constexpr int aidx(int l, int m) { return l * (l - 1) / 2 + (m - 1); }

// ---------------------------------------------------------------------------
__global__ __launch_bounds__(NTHR, 1)
void sht_fused_kernel(const float* __restrict__ pos, int npts,
                      float* __restrict__ out) {
    unsigned long long acc2[55];   // (l,m>0): lo = +m (real), hi = -m (imag)
    float acc0[11];                // m == 0
#pragma unroll
    for (int j = 0; j < 55; ++j) acc2[j] = 0ull;
#pragma unroll
    for (int j = 0; j < 11; ++j) acc0[j] = 0.0f;

    const int stride = gridDim.x * blockDim.x;

    // software-prefetched grid-stride loop
    int i = blockIdx.x * blockDim.x + threadIdx.x;
    bool valid = (i < npts);
    float nx = 0.f, ny = 0.f, nz = 0.f;
    if (valid) {
        nx = pos[3 * i + 0];
        ny = pos[3 * i + 1];
        nz = pos[3 * i + 2];
    }

    while (valid) {
        const float x  = nx;
        const float y  = ny;
        const float z0 = nz;

        // prefetch next point BEFORE the long compute body
        i += stride;
        valid = (i < npts);
        if (valid) {
            nx = pos[3 * i + 0];
            ny = pos[3 * i + 1];
            nz = pos[3 * i + 2];
        }

        const float r2 = fmaf(x, x, fmaf(y, y, z0 * z0));
        const float r  = sqrtf(r2);

        // w[k] = mask * z0 * r^k
        float w[11];
        w[0] = (r2 > 0.0f) ? z0 : 0.0f;
#pragma unroll
        for (int k = 1; k < 11; ++k) w[k] = w[k - 1] * r;

        // h[s] = r^s/s!, broadcast-packed h2
        float h[11];
        unsigned long long h2[11];
        h[0] = 1.0f;
        h2[0] = pack2(1.0f, 1.0f);
        static_for<1, 11>([&](auto sc) {
            constexpr int s = decltype(sc)::value;
            const float rs = r * (float)(1.0 / (double)s);   // FMUL-imm
            h[s] = h[s - 1] * rs;
            h2[s] = pack2(h[s], h[s]);
        });

        // z1^p powers, z1 = (-x/2, -y/2)
        float zr[11], zi[11];
        zr[0] = 1.0f; zi[0] = 0.0f;
        const float ar = -0.5f * x;
        const float ai = -0.5f * y;
#pragma unroll
        for (int p = 1; p < 11; ++p) {
            zr[p] = fmaf(ar, zr[p - 1], -(ai * zi[p - 1]));
            zi[p] = fmaf(ar, zi[p - 1],  (ai * zr[p - 1]));
        }

        // si[q] = zi[q]^2, q <= 5 only (q <= p, p+q <= 10)
        float si[6];
#pragma unroll
        for (int q = 0; q < 6; ++q) si[q] = zi[q] * zi[q];

        // 36 (p,q) pairs, p >= q, k = p+q <= 10
        static_for<0, 11>([&](auto pc) {
            constexpr int p = decltype(pc)::value;
            static_for<0, p + 1>([&](auto qc) {
                constexpr int q = decltype(qc)::value;
                if constexpr (p + q <= 10) {
                    constexpr int k = p + q;
                    constexpr int m = p - q;
                    const float D = fmaf(zr[p], zr[p], -si[q]);   // zr[p]^2 - zi[q]^2
                    const float c = w[k] * cB(p, q);              // FMUL-imm
                    if constexpr (m == 0) {
                        const float Dc = D * c;
                        static_for<k, 11>([&](auto lc) {
                            constexpr int l = decltype(lc)::value;
                            acc0[l] = fmaf(Dc, h[l - k], acc0[l]);
                        });
                    } else {
                        // P carries the (-1)^q sign via operand order
                        float P;
                        if constexpr (q & 1)
                            P = fmaf(zr[p], zi[q], -(zi[p] * zr[q]));
                        else
                            P = fmaf(zi[p], zr[q], -(zr[p] * zi[q]));
                        const unsigned long long DPs = pack2(D * c, P * c);
                        static_for<k, 11>([&](auto lc) {
                            constexpr int l = decltype(lc)::value;
                            acc2[aidx(l, m)] = fma2(DPs, h2[l - k], acc2[aidx(l, m)]);
                        });
                    }
                }
            });
        });
    }

    // ---- block-level reduction: shfl within warp, smem across 8 warps ----
    __shared__ float sred[NTHR / 32][121];
    const int lane = threadIdx.x & 31;
    const int wid  = threadIdx.x >> 5;

    auto wreduce = [&](float v, int j) {
#pragma unroll
        for (int o = 16; o > 0; o >>= 1) v += __shfl_xor_sync(0xffffffffu, v, o);
        if (lane == 0) sred[wid][j] = v;
    };

    static_for<0, 11>([&](auto lc) {
        constexpr int l = decltype(lc)::value;
        wreduce(acc0[l], l * l + l);
        static_for<1, l + 1>([&](auto mc) {
            constexpr int m = decltype(mc)::value;
            float re, im;
            unpack2(acc2[aidx(l, m)], re, im);
            wreduce(re, l * l + l + m);
            wreduce(im, l * l + l - m);
        });
    });
    __syncthreads();

    if (threadIdx.x < 121) {
        float s = 0.0f;
#pragma unroll
        for (int wv = 0; wv < NTHR / 32; ++wv) s += sred[wv][threadIdx.x];
        g_part[threadIdx.x * NBLK + blockIdx.x] = s;
    }

    // ---- last block does the final reduction + epilogue scaling ----
    __threadfence();
    __shared__ int amLast;
    if (threadIdx.x == 0)
        amLast = (atomicAdd(&g_ticket, 1u) == (unsigned)(gridDim.x - 1));
    __syncthreads();

    if (amLast) {
        double s = 0.0;
        const int j = threadIdx.x >> 1;
        const int hb = threadIdx.x & 1;
        if (threadIdx.x < 242) {
            const int b0 = hb * (NBLK / 2);
#pragma unroll 4
            for (int b = b0; b < b0 + NBLK / 2; ++b)
                s += (double)g_part[j * NBLK + b];
        }
        s += __shfl_xor_sync(0xffffffffu, s, 1);
        if (threadIdx.x < 242 && hb == 0) {
            int l = 0;
            while ((l + 1) * (l + 1) <= j) ++l;
            const int M  = j - l * l - l;
            const int am = (M < 0) ? -M : M;
            double f1 = 1.0, f2 = 1.0;
            for (int t = 2; t <= l + am; ++t) f1 *= (double)t;
            for (int t = 2; t <= l - am; ++t) f2 *= (double)t;
            double scale = sqrt(f1) * sqrt(f2) *
                           sqrt((2.0 * l + 1.0) / (4.0 * 3.14159265358979323846));
            if (am) scale *= sqrt(2.0) * ((am & 1) ? -1.0 : 1.0);
            out[j] = (float)(s * scale);
        }
        if (threadIdx.x == 0) g_ticket = 0;   // reset for next graph replay
    }
}

// ---------------------------------------------------------------------------
extern "C" void kernel_launch(void* const* d_in, const int* in_sizes, int n_in,
                              void* d_out, int out_size) {
    const float* pos = (const float*)d_in[0];
    const int npts = in_sizes[0] / 3;
    sht_fused_kernel<<<NBLK, NTHR>>>(pos, npts, (float*)d_out);
}